// round 3
// baseline (speedup 1.0000x reference)
#include <cuda_runtime.h>
#include <math.h>

// ---------------------------------------------------------------------------
// SPDNet collapsed: out = vec(logm(M^T X M)) @ Wsym + b,  M = w1 @ w2 (12x11)
// Both ReEig stages are provably no-ops (lambda_min >= 1e-3 > eps = 1e-4).
// ---------------------------------------------------------------------------

#define NSWEEP 6

__device__ float g_M[12 * 11];       // M = w1 @ w2
__device__ float g_Wsym[52 * 66];    // symmetrized linear weights (upper-tri packed)

__global__ void prep_kernel(const float* __restrict__ w1,
                            const float* __restrict__ w2,
                            const float* __restrict__ w_lin) {
    int t = threadIdx.x;
    // M[i][l] = sum_k w1[i][k] * w2[k][l]
    if (t < 132) {
        int i = t / 11, l = t % 11;
        float acc = 0.f;
        #pragma unroll
        for (int k = 0; k < 12; ++k) acc += w1[i * 12 + k] * w2[k * 11 + l];
        g_M[t] = acc;
    }
    // Wsym[c][t] over packed upper triangle (i<=j) of the 11x11 log-matrix
    for (int idx = t; idx < 52 * 66; idx += blockDim.x) {
        int c = idx / 66, tt = idx % 66;
        int i = 0, rem = tt;
        while (rem >= 11 - i) { rem -= 11 - i; ++i; }
        int j = i + rem;
        float v;
        if (i == j) v = w_lin[c * 121 + i * 11 + i];
        else        v = w_lin[c * 121 + i * 11 + j] + w_lin[c * 121 + j * 11 + i];
        g_Wsym[idx] = v;
    }
}

__global__ __launch_bounds__(256) void spd_main(const float* __restrict__ x,
                                                const float* __restrict__ b_lin,
                                                float* __restrict__ out, int B) {
    __shared__ float Ms[132];
    __shared__ float Ws[52 * 66];
    __shared__ float bs[52];
    for (int i = threadIdx.x; i < 132; i += blockDim.x) Ms[i] = g_M[i];
    for (int i = threadIdx.x; i < 52 * 66; i += blockDim.x) Ws[i] = g_Wsym[i];
    if (threadIdx.x < 52) bs[threadIdx.x] = b_lin[threadIdx.x];
    __syncthreads();

    int b = blockIdx.x * blockDim.x + threadIdx.x;
    if (b >= B) return;

    // ---- T = X @ M  (12x11), X streamed as float4, acc row in registers ----
    const float4* xg = reinterpret_cast<const float4*>(x + (size_t)b * 144);
    float T[132];
    for (int i = 0; i < 12; ++i) {
        float acc[11];
        #pragma unroll
        for (int l = 0; l < 11; ++l) acc[l] = 0.f;
        #pragma unroll
        for (int j4 = 0; j4 < 3; ++j4) {
            float4 v = xg[i * 3 + j4];
            float xs0 = v.x, xs1 = v.y, xs2 = v.z, xs3 = v.w;
            int j = j4 * 4;
            #pragma unroll
            for (int l = 0; l < 11; ++l) acc[l] = fmaf(xs0, Ms[(j + 0) * 11 + l], acc[l]);
            #pragma unroll
            for (int l = 0; l < 11; ++l) acc[l] = fmaf(xs1, Ms[(j + 1) * 11 + l], acc[l]);
            #pragma unroll
            for (int l = 0; l < 11; ++l) acc[l] = fmaf(xs2, Ms[(j + 2) * 11 + l], acc[l]);
            #pragma unroll
            for (int l = 0; l < 11; ++l) acc[l] = fmaf(xs3, Ms[(j + 3) * 11 + l], acc[l]);
        }
        #pragma unroll
        for (int l = 0; l < 11; ++l) T[i * 11 + l] = acc[l];
    }

    // ---- H = M^T T  (11x11 symmetric) ----
    float h[121];
    for (int k = 0; k < 11; ++k) {
        for (int l = k; l < 11; ++l) {
            float acc = 0.f;
            #pragma unroll
            for (int i = 0; i < 12; ++i) acc = fmaf(Ms[i * 11 + k], T[i * 11 + l], acc);
            h[k * 11 + l] = acc;
            h[l * 11 + k] = acc;
        }
    }

    // ---- Jacobi eigendecomposition: H = V diag(lam) V^T ----
    float u[121];
    for (int i = 0; i < 121; ++i) u[i] = 0.f;
    for (int i = 0; i < 11; ++i) u[i * 11 + i] = 1.f;

    for (int sweep = 0; sweep < NSWEEP; ++sweep) {
        for (int p = 0; p < 10; ++p) {
            for (int q = p + 1; q < 11; ++q) {
                float apq = h[p * 11 + q];
                float app = h[p * 11 + p];
                float aqq = h[q * 11 + q];
                if (apq * apq <= 1e-24f * app * aqq) continue;
                float tau = (aqq - app) / (2.f * apq);
                float t   = copysignf(1.f, tau) / (fabsf(tau) + sqrtf(fmaf(tau, tau, 1.f)));
                float c   = rsqrtf(fmaf(t, t, 1.f));
                float s   = t * c;
                // rows p,q: G^T A
                #pragma unroll
                for (int j = 0; j < 11; ++j) {
                    float hpj = h[p * 11 + j], hqj = h[q * 11 + j];
                    h[p * 11 + j] = fmaf(c, hpj, -s * hqj);
                    h[q * 11 + j] = fmaf(s, hpj,  c * hqj);
                }
                // cols p,q: (G^T A) G  + accumulate V = V G
                #pragma unroll
                for (int i2 = 0; i2 < 11; ++i2) {
                    float hip = h[i2 * 11 + p], hiq = h[i2 * 11 + q];
                    h[i2 * 11 + p] = fmaf(c, hip, -s * hiq);
                    h[i2 * 11 + q] = fmaf(s, hip,  c * hiq);
                    float uip = u[i2 * 11 + p], uiq = u[i2 * 11 + q];
                    u[i2 * 11 + p] = fmaf(c, uip, -s * uiq);
                    u[i2 * 11 + q] = fmaf(s, uip,  c * uiq);
                }
            }
        }
    }

    // ---- log eigenvalues ----
    float lw[11];
    #pragma unroll
    for (int m = 0; m < 11; ++m) lw[m] = __logf(fmaxf(h[m * 11 + m], 1e-20f));

    // ---- L = V diag(log lam) V^T, packed upper triangle (66) ----
    float Lp[66];
    {
        int idx = 0;
        for (int i = 0; i < 11; ++i) {
            float wr[11];
            #pragma unroll
            for (int m = 0; m < 11; ++m) wr[m] = u[i * 11 + m] * lw[m];
            for (int j = i; j < 11; ++j) {
                float acc = 0.f;
                #pragma unroll
                for (int m = 0; m < 11; ++m) acc = fmaf(wr[m], u[j * 11 + m], acc);
                Lp[idx++] = acc;
            }
        }
    }

    // ---- linear: out[b][c] = b[c] + sum_k Ws[c][k] * Lp[k], float4 stores ----
    float4* og = reinterpret_cast<float4*>(out + (size_t)b * 52);
    for (int c4 = 0; c4 < 13; ++c4) {
        float accs[4];
        #pragma unroll
        for (int e = 0; e < 4; ++e) {
            int c = c4 * 4 + e;
            float acc = bs[c];
            #pragma unroll 6
            for (int k = 0; k < 66; ++k) acc = fmaf(Ws[c * 66 + k], Lp[k], acc);
            accs[e] = acc;
        }
        float4 r;
        r.x = accs[0]; r.y = accs[1]; r.z = accs[2]; r.w = accs[3];
        og[c4] = r;
    }
}

extern "C" void kernel_launch(void* const* d_in, const int* in_sizes, int n_in,
                              void* d_out, int out_size) {
    const float* x     = (const float*)d_in[0];
    const float* w1    = (const float*)d_in[1];
    const float* w2    = (const float*)d_in[2];
    const float* w_lin = (const float*)d_in[3];
    const float* b_lin = (const float*)d_in[4];
    float* out = (float*)d_out;

    int B = in_sizes[0] / 144;

    prep_kernel<<<1, 256>>>(w1, w2, w_lin);
    int threads = 256;
    int blocks  = (B + threads - 1) / threads;
    spd_main<<<blocks, threads>>>(x, b_lin, out, B);
}

// round 4
// speedup vs baseline: 7.6477x; 7.6477x over previous
#include <cuda_runtime.h>
#include <math.h>

// ---------------------------------------------------------------------------
// SPDNet collapsed: out = vec(logm(M^T X M)) @ Wsym + b,  M = w1 @ w2 (12x11)
// Both ReEig stages are provably no-ops (lambda_min >= 1e-3 > eps = 1e-4).
// This round: fully-unrolled register-resident Jacobi (packed upper triangle),
// branchless rotations, LDS.128 weight streaming.
// ---------------------------------------------------------------------------

#define NSWEEP 6
#define WSK 68   // padded inner dim for the linear layer (66 -> 68 for float4)

__device__ float g_M[12 * 11];        // M = w1 @ w2
__device__ float g_Wsym[52 * WSK];    // symmetrized linear weights, padded

// upper-triangle index, requires i <= j
__device__ __forceinline__ constexpr int TRI(int i, int j) {
    return i * 11 - (i * (i + 1)) / 2 + j;
}
__device__ __forceinline__ constexpr int TRIM(int i, int j) {
    return (i <= j) ? TRI(i, j) : TRI(j, i);
}

__global__ void prep_kernel(const float* __restrict__ w1,
                            const float* __restrict__ w2,
                            const float* __restrict__ w_lin) {
    int t = threadIdx.x;
    if (t < 132) {
        int i = t / 11, l = t % 11;
        float acc = 0.f;
        #pragma unroll
        for (int k = 0; k < 12; ++k) acc += w1[i * 12 + k] * w2[k * 11 + l];
        g_M[t] = acc;
    }
    for (int idx = t; idx < 52 * WSK; idx += blockDim.x) {
        int c = idx / WSK, tt = idx % WSK;
        float v = 0.f;
        if (tt < 66) {
            int i = 0, rem = tt;
            while (rem >= 11 - i) { rem -= 11 - i; ++i; }
            int j = i + rem;
            if (i == j) v = w_lin[c * 121 + i * 11 + i];
            else        v = w_lin[c * 121 + i * 11 + j] + w_lin[c * 121 + j * 11 + i];
        }
        g_Wsym[idx] = v;
    }
}

__global__ __launch_bounds__(128) void spd_main(const float* __restrict__ x,
                                                const float* __restrict__ b_lin,
                                                float* __restrict__ out, int B) {
    __shared__ float Ms[132];
    __shared__ alignas(16) float Ws[52 * WSK];
    __shared__ float bs[52];
    for (int i = threadIdx.x; i < 132; i += blockDim.x) Ms[i] = g_M[i];
    for (int i = threadIdx.x; i < 52 * WSK; i += blockDim.x) Ws[i] = g_Wsym[i];
    if (threadIdx.x < 52) bs[threadIdx.x] = b_lin[threadIdx.x];
    __syncthreads();

    int b = blockIdx.x * blockDim.x + threadIdx.x;
    if (b >= B) return;

    // ---- H = M^T X M, accumulated row-incrementally into packed upper tri ----
    float h[66];
    #pragma unroll
    for (int k = 0; k < 66; ++k) h[k] = 0.f;

    const float4* xg = reinterpret_cast<const float4*>(x + (size_t)b * 144);
    #pragma unroll
    for (int i = 0; i < 12; ++i) {
        float4 v0 = xg[i * 3 + 0];
        float4 v1 = xg[i * 3 + 1];
        float4 v2 = xg[i * 3 + 2];
        float xr[12] = {v0.x, v0.y, v0.z, v0.w,
                        v1.x, v1.y, v1.z, v1.w,
                        v2.x, v2.y, v2.z, v2.w};
        // trow = X[i,:] @ M   (1x11)
        float trow[11];
        #pragma unroll
        for (int l = 0; l < 11; ++l) trow[l] = 0.f;
        #pragma unroll
        for (int j = 0; j < 12; ++j) {
            float xj = xr[j];
            #pragma unroll
            for (int l = 0; l < 11; ++l)
                trow[l] = fmaf(xj, Ms[j * 11 + l], trow[l]);
        }
        // H(upper) += M[i,:]^T x trow
        #pragma unroll
        for (int k = 0; k < 11; ++k) {
            float mik = Ms[i * 11 + k];
            #pragma unroll
            for (int l = k; l < 11; ++l)
                h[TRI(k, l)] = fmaf(mik, trow[l], h[TRI(k, l)]);
        }
    }

    // ---- Jacobi eigendecomposition, fully unrolled sweep (registers only) ----
    float u[121];
    #pragma unroll
    for (int i = 0; i < 121; ++i) u[i] = 0.f;
    #pragma unroll
    for (int i = 0; i < 11; ++i) u[i * 11 + i] = 1.f;

    for (int sweep = 0; sweep < NSWEEP; ++sweep) {
        #pragma unroll
        for (int p = 0; p < 10; ++p) {
            #pragma unroll
            for (int q = p + 1; q < 11; ++q) {
                float apq = h[TRI(p, q)];
                float app = h[TRI(p, p)];
                float aqq = h[TRI(q, q)];
                float tau = __fdividef(aqq - app, 2.f * apq);
                float t   = copysignf(1.f, tau) /
                            (fabsf(tau) + sqrtf(fmaf(tau, tau, 1.f)));
                if (!(fabsf(apq) > 0.f)) t = 0.f;   // apq==0 or NaN -> identity
                float c = rsqrtf(fmaf(t, t, 1.f));
                float s = t * c;
                h[TRI(p, p)] = fmaf(-t, apq, app);
                h[TRI(q, q)] = fmaf( t, apq, aqq);
                h[TRI(p, q)] = 0.f;
                #pragma unroll
                for (int j = 0; j < 11; ++j) {
                    if (j == p || j == q) continue;
                    float hpj = h[TRIM(p, j)];
                    float hqj = h[TRIM(q, j)];
                    h[TRIM(p, j)] = fmaf(c, hpj, -s * hqj);
                    h[TRIM(q, j)] = fmaf(s, hpj,  c * hqj);
                }
                #pragma unroll
                for (int i2 = 0; i2 < 11; ++i2) {
                    float uip = u[i2 * 11 + p], uiq = u[i2 * 11 + q];
                    u[i2 * 11 + p] = fmaf(c, uip, -s * uiq);
                    u[i2 * 11 + q] = fmaf(s, uip,  c * uiq);
                }
            }
        }
    }

    // ---- log eigenvalues ----
    float lw[11];
    #pragma unroll
    for (int m = 0; m < 11; ++m) lw[m] = __logf(fmaxf(h[TRI(m, m)], 1e-20f));

    // ---- L = V diag(log lam) V^T, packed upper triangle (66, padded to 68) ----
    float Lp[WSK];
    Lp[66] = 0.f; Lp[67] = 0.f;
    #pragma unroll
    for (int i = 0; i < 11; ++i) {
        float wr[11];
        #pragma unroll
        for (int m = 0; m < 11; ++m) wr[m] = u[i * 11 + m] * lw[m];
        #pragma unroll
        for (int j = i; j < 11; ++j) {
            float acc = 0.f;
            #pragma unroll
            for (int m = 0; m < 11; ++m) acc = fmaf(wr[m], u[j * 11 + m], acc);
            Lp[TRI(i, j)] = acc;
        }
    }

    // ---- linear: out[b][c] = b[c] + Ws[c][:] . Lp, weights via LDS.128 ----
    const float4* Wv = reinterpret_cast<const float4*>(Ws);
    float4* og = reinterpret_cast<float4*>(out + (size_t)b * 52);
    #pragma unroll
    for (int c4 = 0; c4 < 13; ++c4) {
        float4 r;
        #pragma unroll
        for (int e = 0; e < 4; ++e) {
            int c = c4 * 4 + e;
            float acc = bs[c];
            #pragma unroll
            for (int k4 = 0; k4 < WSK / 4; ++k4) {
                float4 w = Wv[c * (WSK / 4) + k4];
                acc = fmaf(w.x, Lp[k4 * 4 + 0], acc);
                acc = fmaf(w.y, Lp[k4 * 4 + 1], acc);
                acc = fmaf(w.z, Lp[k4 * 4 + 2], acc);
                acc = fmaf(w.w, Lp[k4 * 4 + 3], acc);
            }
            reinterpret_cast<float*>(&r)[e] = acc;
        }
        og[c4] = r;
    }
}

extern "C" void kernel_launch(void* const* d_in, const int* in_sizes, int n_in,
                              void* d_out, int out_size) {
    const float* x     = (const float*)d_in[0];
    const float* w1    = (const float*)d_in[1];
    const float* w2    = (const float*)d_in[2];
    const float* w_lin = (const float*)d_in[3];
    const float* b_lin = (const float*)d_in[4];
    float* out = (float*)d_out;

    int B = in_sizes[0] / 144;

    prep_kernel<<<1, 256>>>(w1, w2, w_lin);
    int threads = 128;
    int blocks  = (B + threads - 1) / threads;
    spd_main<<<blocks, threads>>>(x, b_lin, out, B);
}

// round 5
// speedup vs baseline: 9.9933x; 1.3067x over previous
#include <cuda_runtime.h>
#include <math.h>

// ---------------------------------------------------------------------------
// SPDNet collapsed: out = vec(logm(M^T X M)) @ Wsym + b,  M = w1 @ w2 (12x11)
// Both ReEig stages are provably no-ops (lambda_min >= 1e-3 > eps = 1e-4).
// This round: parallel-ordered (round-robin) Jacobi for 5x ILP on the c/s
// chains, f32x2-packed eigenvector accumulation, NSWEEP 6 -> 5.
// ---------------------------------------------------------------------------

#define NSWEEP 5
#define WSK 68   // padded inner dim for the linear layer (66 -> 68 for float4)

typedef unsigned long long ull;

__device__ float g_M[12 * 11];        // M = w1 @ w2
__device__ float g_Wsym[52 * WSK];    // symmetrized linear weights, padded

// upper-triangle index, requires i <= j
__device__ __forceinline__ constexpr int TRI(int i, int j) {
    return i * 11 - (i * (i + 1)) / 2 + j;
}
__device__ __forceinline__ constexpr int TRIM(int i, int j) {
    return (i <= j) ? TRI(i, j) : TRI(j, i);
}

// ---- packed f32x2 helpers (PTX-only; ptxas never fuses these from C++) ----
__device__ __forceinline__ ull pack2(float lo, float hi) {
    ull r; asm("mov.b64 %0, {%1, %2};" : "=l"(r) : "f"(lo), "f"(hi)); return r;
}
__device__ __forceinline__ void unpack2(ull v, float& lo, float& hi) {
    asm("mov.b64 {%0, %1}, %2;" : "=f"(lo), "=f"(hi) : "l"(v));
}
__device__ __forceinline__ ull fma2(ull a, ull b, ull c) {
    ull d; asm("fma.rn.f32x2 %0, %1, %2, %3;" : "=l"(d) : "l"(a), "l"(b), "l"(c)); return d;
}
__device__ __forceinline__ ull mul2(ull a, ull b) {
    ull d; asm("mul.rn.f32x2 %0, %1, %2;" : "=l"(d) : "l"(a), "l"(b)); return d;
}

__global__ void prep_kernel(const float* __restrict__ w1,
                            const float* __restrict__ w2,
                            const float* __restrict__ w_lin) {
    int t = threadIdx.x;
    if (t < 132) {
        int i = t / 11, l = t % 11;
        float acc = 0.f;
        #pragma unroll
        for (int k = 0; k < 12; ++k) acc += w1[i * 12 + k] * w2[k * 11 + l];
        g_M[t] = acc;
    }
    for (int idx = t; idx < 52 * WSK; idx += blockDim.x) {
        int c = idx / WSK, tt = idx % WSK;
        float v = 0.f;
        if (tt < 66) {
            int i = 0, rem = tt;
            while (rem >= 11 - i) { rem -= 11 - i; ++i; }
            int j = i + rem;
            if (i == j) v = w_lin[c * 121 + i * 11 + i];
            else        v = w_lin[c * 121 + i * 11 + j] + w_lin[c * 121 + j * 11 + i];
        }
        g_Wsym[idx] = v;
    }
}

__global__ __launch_bounds__(128) void spd_main(const float* __restrict__ x,
                                                const float* __restrict__ b_lin,
                                                float* __restrict__ out, int B) {
    __shared__ float Ms[132];
    __shared__ alignas(16) float Ws[52 * WSK];
    __shared__ float bs[52];
    for (int i = threadIdx.x; i < 132; i += blockDim.x) Ms[i] = g_M[i];
    for (int i = threadIdx.x; i < 52 * WSK; i += blockDim.x) Ws[i] = g_Wsym[i];
    if (threadIdx.x < 52) bs[threadIdx.x] = b_lin[threadIdx.x];
    __syncthreads();

    int b = blockIdx.x * blockDim.x + threadIdx.x;
    if (b >= B) return;

    // ---- H = M^T X M, accumulated row-incrementally into packed upper tri ----
    float h[66];
    #pragma unroll
    for (int k = 0; k < 66; ++k) h[k] = 0.f;

    const float4* xg = reinterpret_cast<const float4*>(x + (size_t)b * 144);
    #pragma unroll
    for (int i = 0; i < 12; ++i) {
        float4 v0 = xg[i * 3 + 0];
        float4 v1 = xg[i * 3 + 1];
        float4 v2 = xg[i * 3 + 2];
        float xr[12] = {v0.x, v0.y, v0.z, v0.w,
                        v1.x, v1.y, v1.z, v1.w,
                        v2.x, v2.y, v2.z, v2.w};
        float trow[11];
        #pragma unroll
        for (int l = 0; l < 11; ++l) trow[l] = 0.f;
        #pragma unroll
        for (int j = 0; j < 12; ++j) {
            float xj = xr[j];
            #pragma unroll
            for (int l = 0; l < 11; ++l)
                trow[l] = fmaf(xj, Ms[j * 11 + l], trow[l]);
        }
        #pragma unroll
        for (int k = 0; k < 11; ++k) {
            float mik = Ms[i * 11 + k];
            #pragma unroll
            for (int l = k; l < 11; ++l)
                h[TRI(k, l)] = fmaf(mik, trow[l], h[TRI(k, l)]);
        }
    }

    // ---- V as packed f32x2: u2[col][rowpair], rows (2rp, 2rp+1), row 11 dummy ----
    ull u2[11][6];
    #pragma unroll
    for (int c = 0; c < 11; ++c)
        #pragma unroll
        for (int rp = 0; rp < 6; ++rp)
            u2[c][rp] = pack2((2 * rp == c) ? 1.f : 0.f,
                              (2 * rp + 1 == c) ? 1.f : 0.f);

    // ---- parallel-ordered Jacobi: 11 rounds x 5 disjoint pairs per sweep ----
    for (int sweep = 0; sweep < NSWEEP; ++sweep) {
        #pragma unroll
        for (int r = 0; r < 11; ++r) {
            const int mm = (r * 6) % 11;  // bye element; pairs (mm+k, mm-k)
            float cs_c[5], cs_s[5];
            // batch: all 5 pivots/diagonals are disjoint -> independent chains
            #pragma unroll
            for (int k = 1; k <= 5; ++k) {
                const int a0 = (mm + k) % 11;
                const int b0 = (mm + 11 - k) % 11;
                const int p = (a0 < b0) ? a0 : b0;
                const int q = (a0 < b0) ? b0 : a0;
                float apq = h[TRI(p, q)];
                float app = h[TRI(p, p)];
                float aqq = h[TRI(q, q)];
                float tau = __fdividef(aqq - app, 2.f * apq);
                float t   = copysignf(1.f, tau) /
                            (fabsf(tau) + sqrtf(fmaf(tau, tau, 1.f)));
                if (!(fabsf(apq) > 0.f)) t = 0.f;   // apq==0 or NaN -> identity
                float c = rsqrtf(fmaf(t, t, 1.f));
                cs_c[k - 1] = c;
                cs_s[k - 1] = t * c;
                h[TRI(p, p)] = fmaf(-t, apq, app);
                h[TRI(q, q)] = fmaf( t, apq, aqq);
                h[TRI(p, q)] = 0.f;
            }
            // apply: off-diagonal h updates + packed u updates
            #pragma unroll
            for (int k = 1; k <= 5; ++k) {
                const int a0 = (mm + k) % 11;
                const int b0 = (mm + 11 - k) % 11;
                const int p = (a0 < b0) ? a0 : b0;
                const int q = (a0 < b0) ? b0 : a0;
                const float c = cs_c[k - 1];
                const float s = cs_s[k - 1];
                #pragma unroll
                for (int j = 0; j < 11; ++j) {
                    if (j == p || j == q) continue;
                    float hpj = h[TRIM(p, j)];
                    float hqj = h[TRIM(q, j)];
                    h[TRIM(p, j)] = fmaf(c, hpj, -s * hqj);
                    h[TRIM(q, j)] = fmaf(s, hpj,  c * hqj);
                }
                ull c2  = pack2(c, c);
                ull s2  = pack2(s, s);
                ull ns2 = pack2(-s, -s);
                #pragma unroll
                for (int rp = 0; rp < 6; ++rp) {
                    ull up = u2[p][rp], uq = u2[q][rp];
                    u2[p][rp] = fma2(c2, up, mul2(ns2, uq));
                    u2[q][rp] = fma2(s2, up, mul2(c2, uq));
                }
            }
        }
    }

    // ---- log eigenvalues ----
    float lw[11];
    #pragma unroll
    for (int m = 0; m < 11; ++m) lw[m] = __logf(fmaxf(h[TRI(m, m)], 1e-20f));

    // ---- L = V diag(log lam) V^T, rank-1 accumulation per eigenvector ----
    float Lp[WSK];
    #pragma unroll
    for (int k = 0; k < WSK; ++k) Lp[k] = 0.f;
    #pragma unroll
    for (int m = 0; m < 11; ++m) {
        float um[12];
        #pragma unroll
        for (int rp = 0; rp < 6; ++rp)
            unpack2(u2[m][rp], um[2 * rp], um[2 * rp + 1]);
        float lm = lw[m];
        float vm[11];
        #pragma unroll
        for (int i = 0; i < 11; ++i) vm[i] = um[i] * lm;
        #pragma unroll
        for (int i = 0; i < 11; ++i)
            #pragma unroll
            for (int j = i; j < 11; ++j)
                Lp[TRI(i, j)] = fmaf(vm[i], um[j], Lp[TRI(i, j)]);
    }

    // ---- linear: out[b][c] = b[c] + Ws[c][:] . Lp, weights via LDS.128 ----
    const float4* Wv = reinterpret_cast<const float4*>(Ws);
    float4* og = reinterpret_cast<float4*>(out + (size_t)b * 52);
    #pragma unroll
    for (int c4 = 0; c4 < 13; ++c4) {
        float4 rr;
        #pragma unroll
        for (int e = 0; e < 4; ++e) {
            int c = c4 * 4 + e;
            float acc = bs[c];
            #pragma unroll
            for (int k4 = 0; k4 < WSK / 4; ++k4) {
                float4 w = Wv[c * (WSK / 4) + k4];
                acc = fmaf(w.x, Lp[k4 * 4 + 0], acc);
                acc = fmaf(w.y, Lp[k4 * 4 + 1], acc);
                acc = fmaf(w.z, Lp[k4 * 4 + 2], acc);
                acc = fmaf(w.w, Lp[k4 * 4 + 3], acc);
            }
            reinterpret_cast<float*>(&rr)[e] = acc;
        }
        og[c4] = rr;
    }
}

extern "C" void kernel_launch(void* const* d_in, const int* in_sizes, int n_in,
                              void* d_out, int out_size) {
    const float* x     = (const float*)d_in[0];
    const float* w1    = (const float*)d_in[1];
    const float* w2    = (const float*)d_in[2];
    const float* w_lin = (const float*)d_in[3];
    const float* b_lin = (const float*)d_in[4];
    float* out = (float*)d_out;

    int B = in_sizes[0] / 144;

    prep_kernel<<<1, 256>>>(w1, w2, w_lin);
    int threads = 128;
    int blocks  = (B + threads - 1) / threads;
    spd_main<<<blocks, threads>>>(x, b_lin, out, B);
}